// round 5
// baseline (speedup 1.0000x reference)
#include <cuda_runtime.h>
#include <cstdint>
#include <cstddef>

// Problem constants
#define B_  2
#define S_  400
#define D_  512
#define ROWS (B_ * S_)                  // 800
#define ALIGN_OFF (S_ * B_ * D_)        // 409600

// Scratch (device globals: no allocation allowed)
__device__ float g_wq[ROWS * D_];
__device__ float g_uh[ROWS * D_];
__device__ float g_ctx[ROWS * D_];
__device__ float g_scores[ROWS * S_];

// ---------------------------------------------------------------------------
__device__ __forceinline__ float tanh_fast(float x) {
    float y;
    asm("tanh.approx.f32 %0, %1;" : "=f"(y) : "f"(x));
    return y;
}

__device__ __forceinline__ uint32_t f2tf32(float x) {   // round-to-nearest tf32
    uint32_t r;
    asm("cvt.rna.tf32.f32 %0, %1;" : "=r"(r) : "f"(x));
    return r;
}

__device__ __forceinline__ void mma_tf32(float* d,
                                         uint32_t a0, uint32_t a1, uint32_t a2, uint32_t a3,
                                         uint32_t b0, uint32_t b1) {
    asm volatile(
        "mma.sync.aligned.m16n8k8.row.col.f32.tf32.tf32.f32 "
        "{%0,%1,%2,%3}, {%4,%5,%6,%7}, {%8,%9}, {%0,%1,%2,%3};"
        : "+f"(d[0]), "+f"(d[1]), "+f"(d[2]), "+f"(d[3])
        : "r"(a0), "r"(a1), "r"(a2), "r"(a3), "r"(b0), "r"(b1));
}

struct GemmArgs {
    const float* A;     // [M, KA] row-major, lda
    const float* A2;    // [M, K-KA] row-major, lda (concat tail)
    const float* B;     // [K, N] row-major, ldb
    const float* bias;  // [N] or null
    float* C;
};

// ---------------------------------------------------------------------------
// tf32 mma.sync GEMM, 64x64 CTA tile, 256 threads (8 warps: 2M x 4N, each
// warp 32x16). Shared memory holds operands in MMA *fragment order*, tf32
// pre-converted by the loader, so the mainloop per k-step is
// 3x LDS.128 + 4x HMMA per warp. LDG prefetch distance 2 via register stage.
// blockIdx.z selects g0/g1. cmode 0: C[r*ldc+c]; cmode 1: [T,B,D] scatter.
// ---------------------------------------------------------------------------
__global__ void __launch_bounds__(256, 1) gemm_mma(
    GemmArgs g0, GemmArgs g1, int lda, int KA, int ldb, int ldc, int cmode,
    int M, int N, int K)
{
    __shared__ uint32_t As[2][1024];   // [buf][((mt*2+ks)*32+lane)*4 ..]
    __shared__ uint32_t Bs[2][1024];   // [buf][((ks*4+p)*32+lane)*4 ..]

    const GemmArgs g = blockIdx.z ? g1 : g0;

    const int tid  = threadIdx.x;                 // 0..255
    const int warp = tid >> 5, lane = tid & 31;
    const int q = lane >> 2, r = lane & 3;
    const int wm = warp >> 2;                     // 0..1 : M offset 32*wm
    const int wn = warp & 3;                      // 0..3 : N offset 16*wn
    const int row0 = blockIdx.y * 64;
    const int col0 = blockIdx.x * 64;

    // ---- loader coordinates ----
    // A: thread -> fragment (amt, aks, alane); loads 4 scattered floats.
    const int amt   = tid >> 6;                   // 0..3
    const int aks   = (tid >> 5) & 1;             // 0..1
    const int aq = lane >> 2, ar = lane & 3;
    const int arow0 = row0 + amt * 16 + aq;
    const int arow1 = arow0 + 8;
    const int ar0c = (arow0 < M) ? arow0 : (M - 1);
    const int ar1c = (arow1 < M) ? arow1 : (M - 1);
    const int asm_off = ((amt * 2 + aks) * 32 + lane) * 4;
    // B: thread -> fragment (bks, bp, blane)
    const int bks = tid >> 7;                     // 0..1
    const int bp  = (tid >> 5) & 3;               // 0..3
    const int bcol = col0 + bp * 16 + aq;         // aq == lane>>2
    const int bsm_off = ((bks * 4 + bp) * 32 + lane) * 4;

    float acc[2][2][4];
    #pragma unroll
    for (int i = 0; i < 2; ++i)
        #pragma unroll
        for (int j = 0; j < 2; ++j)
            #pragma unroll
            for (int k = 0; k < 4; ++k) acc[i][j][k] = 0.f;

    const int nc = K >> 4;      // K % 16 == 0 for all calls

    float ra[2][4], rb[2][4];

    auto ldg_chunk = [&](int c, float* va, float* vb) {
        const int k0 = c << 4;
        const float* Ab;
        int kk;
        if (k0 < KA) { Ab = g.A; kk = k0; } else { Ab = g.A2; kk = k0 - KA; }
        const int ka = kk + aks * 8 + ar;
        const float* pa0 = Ab + (size_t)ar0c * lda + ka;
        const float* pa1 = Ab + (size_t)ar1c * lda + ka;
        va[0] = __ldg(pa0);
        va[1] = __ldg(pa1);
        va[2] = __ldg(pa0 + 4);
        va[3] = __ldg(pa1 + 4);
        const int kb = k0 + bks * 8 + ar;
        const float* pb = g.B + (size_t)kb * ldb + bcol;
        vb[0] = __ldg(pb);
        vb[1] = __ldg(pb + 4 * ldb);
        vb[2] = __ldg(pb + 8);
        vb[3] = __ldg(pb + 4 * ldb + 8);
    };

    auto sts_chunk = [&](int buf, const float* va, const float* vb) {
        uint4 ua = make_uint4(f2tf32(va[0]), f2tf32(va[1]), f2tf32(va[2]), f2tf32(va[3]));
        uint4 ub = make_uint4(f2tf32(vb[0]), f2tf32(vb[1]), f2tf32(vb[2]), f2tf32(vb[3]));
        *(uint4*)&As[buf][asm_off] = ua;
        *(uint4*)&Bs[buf][bsm_off] = ub;
    };

    // prologue: chunks 0,1 -> register stage; STS chunk 0
    ldg_chunk(0, ra[0], rb[0]);
    if (nc > 1) ldg_chunk(1, ra[1], rb[1]);
    sts_chunk(0, ra[0], rb[0]);
    __syncthreads();

    for (int c = 0; c < nc; ++c) {
        const int buf = c & 1;
        if (c + 2 < nc) ldg_chunk(c + 2, ra[buf], rb[buf]);   // slot freed by STS last iter

        #pragma unroll
        for (int ks = 0; ks < 2; ++ks) {
            const uint4 a0 = *(const uint4*)&As[buf][(((2 * wm    ) * 2 + ks) * 32 + lane) * 4];
            const uint4 a1 = *(const uint4*)&As[buf][(((2 * wm + 1) * 2 + ks) * 32 + lane) * 4];
            const uint4 bb = *(const uint4*)&Bs[buf][((ks * 4 + wn) * 32 + lane) * 4];
            mma_tf32(acc[0][0], a0.x, a0.y, a0.z, a0.w, bb.x, bb.y);
            mma_tf32(acc[0][1], a0.x, a0.y, a0.z, a0.w, bb.z, bb.w);
            mma_tf32(acc[1][0], a1.x, a1.y, a1.z, a1.w, bb.x, bb.y);
            mma_tf32(acc[1][1], a1.x, a1.y, a1.z, a1.w, bb.z, bb.w);
        }
        __syncthreads();
        if (c + 1 < nc) {
            sts_chunk((c + 1) & 1, ra[(c + 1) & 1], rb[(c + 1) & 1]);
            __syncthreads();
        }
    }

    // ---- epilogue ----
    float bvals[2][2];
    #pragma unroll
    for (int nt = 0; nt < 2; ++nt) {
        const int cc = col0 + wn * 16 + nt * 8 + r * 2;
        bvals[nt][0] = g.bias ? __ldg(g.bias + cc)     : 0.f;
        bvals[nt][1] = g.bias ? __ldg(g.bias + cc + 1) : 0.f;
    }
    #pragma unroll
    for (int mt = 0; mt < 2; ++mt) {
        #pragma unroll
        for (int rh = 0; rh < 2; ++rh) {
            const int rr = row0 + wm * 32 + mt * 16 + rh * 8 + q;
            if (rr >= M) continue;
            float* rowp;
            if (cmode == 0) rowp = g.C + (size_t)rr * ldc;
            else {
                const int t = rr % S_, bb = rr / S_;
                rowp = g.C + (size_t)t * (B_ * D_) + (size_t)bb * D_;
            }
            #pragma unroll
            for (int nt = 0; nt < 2; ++nt) {
                const int cc = col0 + wn * 16 + nt * 8 + r * 2;
                float2 o;
                o.x = acc[mt][nt][rh * 2 + 0] + bvals[nt][0];
                o.y = acc[mt][nt][rh * 2 + 1] + bvals[nt][1];
                *(float2*)(rowp + cc) = o;
            }
        }
    }
}

// ---------------------------------------------------------------------------
// Scores: score[b,t,s] = sum_e v[e] * tanh(wq[b,t,e] + uh[b,s,e])
// 8 t per CTA; each warp processes 4 s at a time (q reused from regs).
// grid: (5, 50, 2), 256 threads. MUFU(tanh)-bound by design.
// ---------------------------------------------------------------------------
__global__ void __launch_bounds__(256) scores_kernel(
    const float* __restrict__ wq, const float* __restrict__ uh,
    const float* __restrict__ v, float* __restrict__ scores)
{
    const int b = blockIdx.z, t0 = blockIdx.y * 8;
    const int sbase = blockIdx.x * 96;
    __shared__ float qsm[8][D_];
    __shared__ float vsm[D_];
    const int tid = threadIdx.x;
    for (int i = tid; i < 8 * D_; i += 256)
        qsm[i >> 9][i & 511] = wq[((size_t)(b * S_ + t0 + (i >> 9))) * D_ + (i & 511)];
    for (int i = tid; i < D_; i += 256) vsm[i] = v[i];
    __syncthreads();
    const int warp = tid >> 5, lane = tid & 31;

    for (int sg = 0; sg < 3; ++sg) {
        const int s0 = sbase + sg * 32 + warp * 4;
        const float* up[4];
        #pragma unroll
        for (int j = 0; j < 4; ++j) {
            int sj = s0 + j; if (sj > S_ - 1) sj = S_ - 1;   // clamp (discard at store)
            up[j] = uh + ((size_t)b * S_ + sj) * D_;
        }
        float acc[8][4];
        #pragma unroll
        for (int t = 0; t < 8; ++t)
            #pragma unroll
            for (int j = 0; j < 4; ++j) acc[t][j] = 0.f;

        for (int i = 0; i < 16; ++i) {
            const int e = i * 32 + lane;
            const float ve = vsm[e];
            float qv[8];
            #pragma unroll
            for (int t = 0; t < 8; ++t) qv[t] = qsm[t][e];
            #pragma unroll
            for (int j = 0; j < 4; ++j) {
                const float u = __ldg(up[j] + e);
                #pragma unroll
                for (int t = 0; t < 8; ++t)
                    acc[t][j] = fmaf(ve, tanh_fast(qv[t] + u), acc[t][j]);
            }
        }
        #pragma unroll
        for (int t = 0; t < 8; ++t)
            #pragma unroll
            for (int j = 0; j < 4; ++j) {
                float a = acc[t][j];
                a += __shfl_xor_sync(0xffffffffu, a, 16);
                a += __shfl_xor_sync(0xffffffffu, a, 8);
                a += __shfl_xor_sync(0xffffffffu, a, 4);
                a += __shfl_xor_sync(0xffffffffu, a, 2);
                a += __shfl_xor_sync(0xffffffffu, a, 1);
                if (lane == t * 4 + j && s0 + j < S_)
                    scores[((size_t)(b * S_ + t0 + t)) * S_ + s0 + j] = a;
            }
    }
}

// ---------------------------------------------------------------------------
// Masked softmax per (b,t) row; writes align to d_out in [t,B,S] layout.
// ---------------------------------------------------------------------------
__global__ void softmax_kernel(const float* __restrict__ scores, const int* __restrict__ lens,
                               float* __restrict__ align_out)
{
    const int t = blockIdx.x;
    const int b = blockIdx.y;
    const int len = lens[b];
    const int tid = threadIdx.x;   // 128

    __shared__ float sm[S_];
    __shared__ float red[4];

    const float* srow = scores + ((size_t)(b * S_ + t)) * S_;

    float mx = -1e30f;
    for (int s = tid; s < S_; s += 128) {
        const bool ok = (s < len) && (s != t);
        const float val = ok ? srow[s] : -1e30f;
        sm[s] = val;
        mx = fmaxf(mx, val);
    }
    #pragma unroll
    for (int o = 16; o; o >>= 1) mx = fmaxf(mx, __shfl_xor_sync(0xffffffffu, mx, o));
    if ((tid & 31) == 0) red[tid >> 5] = mx;
    __syncthreads();
    const float bm = fmaxf(fmaxf(red[0], red[1]), fmaxf(red[2], red[3]));
    __syncthreads();

    float sum = 0.0f;
    for (int s = tid; s < S_; s += 128) {
        const float val = sm[s];
        const float e = (val > -1e29f) ? __expf(val - bm) : 0.0f;
        sm[s] = e;
        sum += e;
    }
    #pragma unroll
    for (int o = 16; o; o >>= 1) sum += __shfl_xor_sync(0xffffffffu, sum, o);
    if ((tid & 31) == 0) red[tid >> 5] = sum;
    __syncthreads();
    const float inv = 1.0f / (red[0] + red[1] + red[2] + red[3]);

    for (int s = tid; s < S_; s += 128)
        align_out[(size_t)t * (B_ * S_) + (size_t)b * S_ + s] = sm[s] * inv;
}

// ---------------------------------------------------------------------------
extern "C" void kernel_launch(void* const* d_in, const int* in_sizes, int n_in,
                              void* d_out, int out_size)
{
    const float* input  = (const float*)d_in[0];
    const float* memory = (const float*)d_in[1];
    const int*   lens   = (const int*)d_in[2];
    const float* Wq     = (const float*)d_in[3];
    const float* bq     = (const float*)d_in[4];
    const float* Wc     = (const float*)d_in[5];
    const float* v      = (const float*)d_in[6];
    const float* Wout   = (const float*)d_in[7];
    const float* bout   = (const float*)d_in[8];
    float* out = (float*)d_out;

    float *wq_p, *uh_p, *ctx_p, *sc_p;
    cudaGetSymbolAddress((void**)&wq_p,  g_wq);
    cudaGetSymbolAddress((void**)&uh_p,  g_uh);
    cudaGetSymbolAddress((void**)&ctx_p, g_ctx);
    cudaGetSymbolAddress((void**)&sc_p,  g_scores);

    // 1) fused: z=0 -> wq = input@Wq + bq; z=1 -> uh = memory@Wc
    {
        GemmArgs gq{input,  input,  Wq, bq,      wq_p};
        GemmArgs gu{memory, memory, Wc, nullptr, uh_p};
        gemm_mma<<<dim3(8, 13, 2), 256>>>(gq, gu, 512, 512, 512, 512, 0, 800, 512, 512);
    }
    // 2) scores
    scores_kernel<<<dim3(5, 50, 2), 256>>>(wq_p, uh_p, v, sc_p);
    // 3) masked softmax -> align (d_out tail)
    softmax_kernel<<<dim3(400, 2), 128>>>(sc_p, lens, out + ALIGN_OFF);
    // 4) context: c[b] = align[b] @ memory[b]  (align rows stride 800; z = batch)
    {
        GemmArgs c0{out + ALIGN_OFF,      out + ALIGN_OFF,      memory,           nullptr, ctx_p};
        GemmArgs c1{out + ALIGN_OFF + S_, out + ALIGN_OFF + S_, memory + S_ * D_, nullptr, ctx_p + S_ * D_};
        gemm_mma<<<dim3(8, 7, 2), 256>>>(c0, c1, 800, 400, 512, 512, 0, 400, 512, 400);
    }
    // 5) attn_h = [ctx | input] @ Wout + bout -> [T,B,D] in d_out
    {
        GemmArgs go{ctx_p, input, Wout, bout, out};
        gemm_mma<<<dim3(8, 13, 1), 256>>>(go, go, 512, 512, 512, 512, 1, 800, 512, 1024);
    }
}

// round 6
// speedup vs baseline: 1.2231x; 1.2231x over previous
#include <cuda_runtime.h>
#include <cstdint>
#include <cstddef>

// Problem constants
#define B_  2
#define S_  400
#define D_  512
#define ROWS (B_ * S_)                  // 800
#define ALIGN_OFF (S_ * B_ * D_)        // 409600

// Scratch (device globals: no allocation allowed)
__device__ float g_wq[ROWS * D_];
__device__ float g_uh[ROWS * D_];
__device__ float g_ctx[ROWS * D_];
__device__ float g_scores[ROWS * S_];

// ---------------------------------------------------------------------------
__device__ __forceinline__ float tanh_fast(float x) {
    float y;
    asm("tanh.approx.f32 %0, %1;" : "=f"(y) : "f"(x));
    return y;
}

__device__ __forceinline__ uint32_t smem_u32(const void* p) {
    uint32_t a;
    asm("{ .reg .u64 t; cvta.to.shared.u64 t, %1; cvt.u32.u64 %0, t; }"
        : "=r"(a) : "l"(p));
    return a;
}

__device__ __forceinline__ uint32_t f2tf32(float x) {   // round-to-nearest tf32
    uint32_t r;
    asm("cvt.rna.tf32.f32 %0, %1;" : "=r"(r) : "f"(x));
    return r;
}

__device__ __forceinline__ void cp_async16(uint32_t dst, const void* src, uint32_t src_bytes) {
    asm volatile("cp.async.ca.shared.global [%0], [%1], 16, %2;"
                 :: "r"(dst), "l"(src), "r"(src_bytes) : "memory");
}

__device__ __forceinline__ void mma_tf32(float* d,
                                         uint32_t a0, uint32_t a1, uint32_t a2, uint32_t a3,
                                         uint32_t b0, uint32_t b1) {
    asm volatile(
        "mma.sync.aligned.m16n8k8.row.col.f32.tf32.tf32.f32 "
        "{%0,%1,%2,%3}, {%4,%5,%6,%7}, {%8,%9}, {%0,%1,%2,%3};"
        : "+f"(d[0]), "+f"(d[1]), "+f"(d[2]), "+f"(d[3])
        : "r"(a0), "r"(a1), "r"(a2), "r"(a3), "r"(b0), "r"(b1));
}

struct GemmArgs {
    const float* A;     // [M, KA] row-major, lda
    const float* A2;    // [M, K-KA] row-major, lda (concat tail)
    const float* B;     // [K, N] row-major, ldb
    const float* bias;  // [N] or null
    float* C;
};

// ---------------------------------------------------------------------------
// tf32 mma.sync GEMM, 64x64 CTA tile, 256 threads (8 warps: 2M x 4N, each
// warp 32x16). BK=16, cp.async double-buffered (R4 loader, coalesced 16B).
// blockIdx.z selects g0/g1. cmode 0: C[r*ldc+c]; cmode 1: [T,B,D] scatter.
// ---------------------------------------------------------------------------
#define ASTR 20
#define BSTR 72

__global__ void __launch_bounds__(256, 1) gemm_mma64(
    GemmArgs g0, GemmArgs g1, int lda, int KA, int ldb, int ldc, int cmode,
    int M, int N, int K)
{
    __shared__ float As[2][64][ASTR];
    __shared__ float Bs[2][16][BSTR];

    const GemmArgs g = blockIdx.z ? g1 : g0;

    const int tid  = threadIdx.x;                  // 0..255
    const int warp = tid >> 5, lane = tid & 31;
    const int q = lane >> 2, r = lane & 3;
    const int wm = warp >> 2;                      // 0..1 : M offset 32*wm
    const int wn = warp & 3;                       // 0..3 : N offset 16*wn
    const int row0 = blockIdx.y * 64;
    const int col0 = blockIdx.x * 64;

    const uint32_t asm_base = smem_u32(&As[0][0][0]);
    const uint32_t bsm_base = smem_u32(&Bs[0][0][0]);

    float acc[2][2][4];
    #pragma unroll
    for (int i = 0; i < 2; ++i)
        #pragma unroll
        for (int j = 0; j < 2; ++j)
            #pragma unroll
            for (int k = 0; k < 4; ++k) acc[i][j][k] = 0.f;

    const int nc = K >> 4;     // K % 16 == 0 for all calls

    // loader coords (1 A chunk + 1 B chunk per thread per stage)
    const int arow = tid >> 2;            // 0..63
    const int ak   = (tid & 3) << 2;      // 0,4,8,12
    const int ar_g = row0 + arow;
    const int arc  = (ar_g < M) ? ar_g : (M - 1);
    const uint32_t apred = (ar_g < M) ? 16u : 0u;
    const int brow = tid >> 4;            // 0..15
    const int bn   = (tid & 15) << 2;     // 0..60

    auto load_stage = [&](int chunk, int buf) {
        const int k0 = chunk << 4;
        {
            const int kk = k0 + ak;
            const float* src = (kk < KA) ? g.A  + (size_t)arc * lda + kk
                                         : g.A2 + (size_t)arc * lda + (kk - KA);
            const uint32_t dst = asm_base +
                (uint32_t)(buf * 64 * ASTR + arow * ASTR + ak) * 4u;
            cp_async16(dst, src, apred);
        }
        {
            const float* src = g.B + (size_t)(k0 + brow) * ldb + col0 + bn;
            const uint32_t dst = bsm_base +
                (uint32_t)(buf * 16 * BSTR + brow * BSTR + bn) * 4u;
            cp_async16(dst, src, 16u);
        }
        asm volatile("cp.async.commit_group;" ::: "memory");
    };

    load_stage(0, 0);

    for (int c = 0; c < nc; ++c) {
        const int buf = c & 1;
        if (c + 1 < nc) {
            load_stage(c + 1, (c + 1) & 1);
            asm volatile("cp.async.wait_group 1;" ::: "memory");
        } else {
            asm volatile("cp.async.wait_group 0;" ::: "memory");
        }
        __syncthreads();

        #pragma unroll
        for (int ks = 0; ks < 2; ++ks) {
            const int kb = ks * 8;
            uint32_t af[2][4];
            #pragma unroll
            for (int mt = 0; mt < 2; ++mt) {
                const int mrow = wm * 32 + mt * 16 + q;
                af[mt][0] = f2tf32(As[buf][mrow    ][kb + r    ]);
                af[mt][1] = f2tf32(As[buf][mrow + 8][kb + r    ]);
                af[mt][2] = f2tf32(As[buf][mrow    ][kb + r + 4]);
                af[mt][3] = f2tf32(As[buf][mrow + 8][kb + r + 4]);
            }
            uint32_t bf[2][2];
            #pragma unroll
            for (int nt = 0; nt < 2; ++nt) {
                const int ncol = wn * 16 + nt * 8 + q;
                bf[nt][0] = f2tf32(Bs[buf][kb + r    ][ncol]);
                bf[nt][1] = f2tf32(Bs[buf][kb + r + 4][ncol]);
            }
            #pragma unroll
            for (int mt = 0; mt < 2; ++mt)
                #pragma unroll
                for (int nt = 0; nt < 2; ++nt)
                    mma_tf32(acc[mt][nt],
                             af[mt][0], af[mt][1], af[mt][2], af[mt][3],
                             bf[nt][0], bf[nt][1]);
        }
        __syncthreads();
    }

    // ---- epilogue ----
    float bvals[2][2];
    #pragma unroll
    for (int nt = 0; nt < 2; ++nt) {
        const int cc = col0 + wn * 16 + nt * 8 + r * 2;
        bvals[nt][0] = g.bias ? __ldg(g.bias + cc)     : 0.f;
        bvals[nt][1] = g.bias ? __ldg(g.bias + cc + 1) : 0.f;
    }
    #pragma unroll
    for (int mt = 0; mt < 2; ++mt) {
        #pragma unroll
        for (int rh = 0; rh < 2; ++rh) {
            const int rr = row0 + wm * 32 + mt * 16 + rh * 8 + q;
            if (rr >= M) continue;
            float* rowp;
            if (cmode == 0) rowp = g.C + (size_t)rr * ldc;
            else {
                const int t = rr % S_, bb = rr / S_;
                rowp = g.C + (size_t)t * (B_ * D_) + (size_t)bb * D_;
            }
            #pragma unroll
            for (int nt = 0; nt < 2; ++nt) {
                const int cc = col0 + wn * 16 + nt * 8 + r * 2;
                float2 o;
                o.x = acc[mt][nt][rh * 2 + 0] + bvals[nt][0];
                o.y = acc[mt][nt][rh * 2 + 1] + bvals[nt][1];
                *(float2*)(rowp + cc) = o;
            }
        }
    }
}

// ---------------------------------------------------------------------------
// Scores: score[b,t,s] = sum_e v[e] * tanh(wq[b,t,e] + uh[b,s,e])
// 8 t per CTA; each warp processes 4 s at a time (q reused from regs).
// grid: (5, 50, 2), 256 threads. MUFU(tanh)-bound by design.
// ---------------------------------------------------------------------------
__global__ void __launch_bounds__(256) scores_kernel(
    const float* __restrict__ wq, const float* __restrict__ uh,
    const float* __restrict__ v, float* __restrict__ scores)
{
    const int b = blockIdx.z, t0 = blockIdx.y * 8;
    const int sbase = blockIdx.x * 96;
    __shared__ float qsm[8][D_];
    __shared__ float vsm[D_];
    const int tid = threadIdx.x;
    for (int i = tid; i < 8 * D_; i += 256)
        qsm[i >> 9][i & 511] = wq[((size_t)(b * S_ + t0 + (i >> 9))) * D_ + (i & 511)];
    for (int i = tid; i < D_; i += 256) vsm[i] = v[i];
    __syncthreads();
    const int warp = tid >> 5, lane = tid & 31;

    for (int sg = 0; sg < 3; ++sg) {
        const int s0 = sbase + sg * 32 + warp * 4;
        const float* up[4];
        #pragma unroll
        for (int j = 0; j < 4; ++j) {
            int sj = s0 + j; if (sj > S_ - 1) sj = S_ - 1;   // clamp (discard at store)
            up[j] = uh + ((size_t)b * S_ + sj) * D_;
        }
        float acc[8][4];
        #pragma unroll
        for (int t = 0; t < 8; ++t)
            #pragma unroll
            for (int j = 0; j < 4; ++j) acc[t][j] = 0.f;

        for (int i = 0; i < 16; ++i) {
            const int e = i * 32 + lane;
            const float ve = vsm[e];
            float qv[8];
            #pragma unroll
            for (int t = 0; t < 8; ++t) qv[t] = qsm[t][e];
            #pragma unroll
            for (int j = 0; j < 4; ++j) {
                const float u = __ldg(up[j] + e);
                #pragma unroll
                for (int t = 0; t < 8; ++t)
                    acc[t][j] = fmaf(ve, tanh_fast(qv[t] + u), acc[t][j]);
            }
        }
        #pragma unroll
        for (int t = 0; t < 8; ++t)
            #pragma unroll
            for (int j = 0; j < 4; ++j) {
                float a = acc[t][j];
                a += __shfl_xor_sync(0xffffffffu, a, 16);
                a += __shfl_xor_sync(0xffffffffu, a, 8);
                a += __shfl_xor_sync(0xffffffffu, a, 4);
                a += __shfl_xor_sync(0xffffffffu, a, 2);
                a += __shfl_xor_sync(0xffffffffu, a, 1);
                if (lane == t * 4 + j && s0 + j < S_)
                    scores[((size_t)(b * S_ + t0 + t)) * S_ + s0 + j] = a;
            }
    }
}

// ---------------------------------------------------------------------------
// Masked softmax per (b,t) row; writes align to d_out in [t,B,S] layout.
// ---------------------------------------------------------------------------
__global__ void softmax_kernel(const float* __restrict__ scores, const int* __restrict__ lens,
                               float* __restrict__ align_out)
{
    const int t = blockIdx.x;
    const int b = blockIdx.y;
    const int len = lens[b];
    const int tid = threadIdx.x;   // 128

    __shared__ float sm[S_];
    __shared__ float red[4];

    const float* srow = scores + ((size_t)(b * S_ + t)) * S_;

    float mx = -1e30f;
    for (int s = tid; s < S_; s += 128) {
        const bool ok = (s < len) && (s != t);
        const float val = ok ? srow[s] : -1e30f;
        sm[s] = val;
        mx = fmaxf(mx, val);
    }
    #pragma unroll
    for (int o = 16; o; o >>= 1) mx = fmaxf(mx, __shfl_xor_sync(0xffffffffu, mx, o));
    if ((tid & 31) == 0) red[tid >> 5] = mx;
    __syncthreads();
    const float bm = fmaxf(fmaxf(red[0], red[1]), fmaxf(red[2], red[3]));
    __syncthreads();

    float sum = 0.0f;
    for (int s = tid; s < S_; s += 128) {
        const float val = sm[s];
        const float e = (val > -1e29f) ? __expf(val - bm) : 0.0f;
        sm[s] = e;
        sum += e;
    }
    #pragma unroll
    for (int o = 16; o; o >>= 1) sum += __shfl_xor_sync(0xffffffffu, sum, o);
    if ((tid & 31) == 0) red[tid >> 5] = sum;
    __syncthreads();
    const float inv = 1.0f / (red[0] + red[1] + red[2] + red[3]);

    for (int s = tid; s < S_; s += 128)
        align_out[(size_t)t * (B_ * S_) + (size_t)b * S_ + s] = sm[s] * inv;
}

// ---------------------------------------------------------------------------
extern "C" void kernel_launch(void* const* d_in, const int* in_sizes, int n_in,
                              void* d_out, int out_size)
{
    const float* input  = (const float*)d_in[0];
    const float* memory = (const float*)d_in[1];
    const int*   lens   = (const int*)d_in[2];
    const float* Wq     = (const float*)d_in[3];
    const float* bq     = (const float*)d_in[4];
    const float* Wc     = (const float*)d_in[5];
    const float* v      = (const float*)d_in[6];
    const float* Wout   = (const float*)d_in[7];
    const float* bout   = (const float*)d_in[8];
    float* out = (float*)d_out;

    float *wq_p, *uh_p, *ctx_p, *sc_p;
    cudaGetSymbolAddress((void**)&wq_p,  g_wq);
    cudaGetSymbolAddress((void**)&uh_p,  g_uh);
    cudaGetSymbolAddress((void**)&ctx_p, g_ctx);
    cudaGetSymbolAddress((void**)&sc_p,  g_scores);

    // 1) fused: z=0 -> wq = input@Wq + bq; z=1 -> uh = memory@Wc
    {
        GemmArgs gq{input,  input,  Wq, bq,      wq_p};
        GemmArgs gu{memory, memory, Wc, nullptr, uh_p};
        gemm_mma64<<<dim3(8, 13, 2), 256>>>(gq, gu, 512, 512, 512, 512, 0, 800, 512, 512);
    }
    // 2) scores
    scores_kernel<<<dim3(5, 50, 2), 256>>>(wq_p, uh_p, v, sc_p);
    // 3) masked softmax -> align (d_out tail)
    softmax_kernel<<<dim3(400, 2), 128>>>(sc_p, lens, out + ALIGN_OFF);
    // 4) context: c[b] = align[b] @ memory[b]  (align rows stride 800; z = batch)
    {
        GemmArgs c0{out + ALIGN_OFF,      out + ALIGN_OFF,      memory,           nullptr, ctx_p};
        GemmArgs c1{out + ALIGN_OFF + S_, out + ALIGN_OFF + S_, memory + S_ * D_, nullptr, ctx_p + S_ * D_};
        gemm_mma64<<<dim3(8, 7, 2), 256>>>(c0, c1, 800, 400, 512, 512, 0, 400, 512, 400);
    }
    // 5) attn_h = [ctx | input] @ Wout + bout -> [T,B,D] in d_out
    {
        GemmArgs go{ctx_p, input, Wout, bout, out};
        gemm_mma64<<<dim3(8, 13, 1), 256>>>(go, go, 512, 512, 512, 512, 1, 800, 512, 1024);
    }
}